// round 4
// baseline (speedup 1.0000x reference)
#include <cuda_runtime.h>

#define CRF_B 128
#define CRF_S 1024
#define CRF_T 128
#define CRF_SOS 0
#define CRF_EOS 1
#define NT 128

typedef unsigned long long u64;

__device__ float g_part[CRF_B];   // per-batch (partition - score), no atomics

__device__ __forceinline__ u64 pack2(float lo, float hi) {
    u64 r; asm("mov.b64 %0,{%1,%2};" : "=l"(r) : "f"(lo), "f"(hi)); return r;
}
__device__ __forceinline__ u64 fma2(u64 a, u64 b, u64 c) {
    u64 d; asm("fma.rn.f32x2 %0,%1,%2,%3;" : "=l"(d) : "l"(a), "l"(b), "l"(c)); return d;
}
__device__ __forceinline__ u64 add2(u64 a, u64 b) {
    u64 d; asm("add.rn.f32x2 %0,%1,%2;" : "=l"(d) : "l"(a), "l"(b)); return d;
}
__device__ __forceinline__ void unpack2(u64 v, float& lo, float& hi) {
    asm("mov.b64 {%0,%1},%2;" : "=f"(lo), "=f"(hi) : "l"(v));
}

// One CRF step.
// APPLY: fold the renorm scale published last step; the scale path (LDS red_sm,
//        max, RCP, two muls, logf) is INDEPENDENT of the dot product, so the
//        scheduler overlaps it with the FMA chain — zero added chain depth.
//        red_sm is pre-seeded to 1.0 so the first apply is an exact no-op.
// PUBLISH: CTA max of pnew via REDUX (p>=0 -> fp32 max == u32 bit-pattern max).
template<bool APPLY, bool PUBLISH>
__device__ __forceinline__ void crf_step(
    float (*p_sm)[CRF_T], float* red_sm, const u64* Ereg,
    int& buf, float& pcur, float& Ccum,
    float eexp_t, float m, int j, int lane, int warp)
{
    const ulonglong2* pq = (const ulonglong2*)p_sm[buf];
    u64 a0 = 0, a1 = 0, a2 = 0, a3 = 0;
#pragma unroll
    for (int m2 = 0; m2 < CRF_T / 4; m2 += 2) {
        ulonglong2 q0 = pq[m2];
        ulonglong2 q1 = pq[m2 + 1];
        a0 = fma2(q0.x, Ereg[2 * m2 + 0], a0);
        a1 = fma2(q0.y, Ereg[2 * m2 + 1], a1);
        a2 = fma2(q1.x, Ereg[2 * m2 + 2], a2);
        a3 = fma2(q1.y, Ereg[2 * m2 + 3], a3);
    }

    float ee = eexp_t;           // emission factor (pre-scaled in APPLY steps)
    float pc = pcur;             // masked-retention value (pre-scaled in APPLY)
    if (APPLY) {                 // alpha = log(p) + Ccum preserved exactly
        float M   = fmaxf(fmaxf(red_sm[0], red_sm[1]), fmaxf(red_sm[2], red_sm[3]));
        float inv = 1.0f / M;
        Ccum += __logf(M);
        ee = inv * eexp_t;       // scale folded into the one existing multiply
        pc = inv * pcur;
    }

    u64 s2 = add2(add2(a0, a1), add2(a2, a3));
    float slo, shi;
    unpack2(s2, slo, shi);
    float ssum = slo + shi;

    float v    = ssum * ee;
    float pnew = (m > 0.5f) ? v : pc;   // masked step keeps alphas unchanged

    if (PUBLISH) {
        unsigned mx = __reduce_max_sync(0xffffffffu, __float_as_uint(pnew));
        if (lane == 0) red_sm[warp] = __uint_as_float(mx);
    }

    buf ^= 1;
    p_sm[buf][j] = pnew;
    pcur = pnew;
    __syncthreads();   // publishes p_sm AND red_sm together (one barrier per step)
}

__global__ void __launch_bounds__(NT, 1) crf_kernel(
    const float* __restrict__ em, const float* __restrict__ trans,
    const float* __restrict__ mask, const int* __restrict__ tags)
{
    __shared__ __align__(16) float p_sm[2][CRF_T];
    __shared__ float msk_sm[CRF_S];
    __shared__ float red_sm[8];

    const int j    = threadIdx.x;
    const int b    = blockIdx.x;
    const int lane = j & 31;
    const int warp = j >> 5;
    const float* emb = em + (size_t)b * CRF_S * CRF_T;

    // ---- E column (exp of transition column j) in registers: 64 packed f32x2 ----
    u64 Ereg[CRF_T / 2];
#pragma unroll
    for (int k = 0; k < CRF_T / 2; ++k) {
        float a = __expf(trans[(2 * k) * CRF_T + j]);
        float c = __expf(trans[(2 * k + 1) * CRF_T + j]);
        Ereg[k] = pack2(a, c);
    }

    for (int s = j; s < CRF_S; s += NT) msk_sm[s] = mask[b * CRF_S + s];
    if (j < 4) red_sm[j] = 1.0f;      // identity renorm for the first apply

    // ---- alpha_0 in exp domain ----
    float pcur = __expf(trans[CRF_SOS * CRF_T + j] + emb[j]);
    p_sm[0][j] = pcur;

    // ---- emission register pipeline: eexp ready rows 1..4, raw in flight 5..8 ----
    float eexp[4], eraw[4];
#pragma unroll
    for (int u = 0; u < 4; ++u) eexp[u] = __expf(emb[(1 + u) * CRF_T + j]);
#pragma unroll
    for (int u = 0; u < 4; ++u) eraw[u] = emb[(5 + u) * CRF_T + j];

    float Ccum = 0.0f;
    int buf = 0;
    __syncthreads();

    // ---- main scan: 255 blocks of 4 steps cover t = 1..1020 ----
    for (int blk = 0; blk < (CRF_S - 4) / 4; ++blk) {
        const int t0 = 1 + blk * 4;

        // hoist mask values off-chain into registers
        float m0 = msk_sm[t0 + 0], m1 = msk_sm[t0 + 1];
        float m2 = msk_sm[t0 + 2], m3 = msk_sm[t0 + 3];

        float enew[4];
#pragma unroll
        for (int u = 0; u < 4; ++u) enew[u] = eraw[u];     // rows t0+4..t0+7 (arrived)
#pragma unroll
        for (int u = 0; u < 4; ++u) {                      // issue rows t0+8..t0+11
            int r = t0 + 8 + u;
            eraw[u] = (r < CRF_S) ? emb[r * CRF_T + j] : 0.0f;
        }

        crf_step<true,  false>(p_sm, red_sm, Ereg, buf, pcur, Ccum, eexp[0], m0, j, lane, warp);
        crf_step<false, false>(p_sm, red_sm, Ereg, buf, pcur, Ccum, eexp[1], m1, j, lane, warp);
        crf_step<false, false>(p_sm, red_sm, Ereg, buf, pcur, Ccum, eexp[2], m2, j, lane, warp);
        crf_step<false, true >(p_sm, red_sm, Ereg, buf, pcur, Ccum, eexp[3], m3, j, lane, warp);

#pragma unroll
        for (int u = 0; u < 4; ++u) eexp[u] = __expf(enew[u]);   // off-chain convert
    }

    // ---- epilogue: t = 1021..1023 (apply pending renorm from t=1020 at first) ----
    crf_step<true,  false>(p_sm, red_sm, Ereg, buf, pcur, Ccum, eexp[0], msk_sm[CRF_S - 3], j, lane, warp);
    crf_step<false, false>(p_sm, red_sm, Ereg, buf, pcur, Ccum, eexp[1], msk_sm[CRF_S - 2], j, lane, warp);
    crf_step<false, false>(p_sm, red_sm, Ereg, buf, pcur, Ccum, eexp[2], msk_sm[CRF_S - 1], j, lane, warp);

    // ---- partition = Ccum + log( sum_j p_j * exp(T[j, EOS]) ) ----
    float vterm = pcur * __expf(trans[j * CRF_T + CRF_EOS]);
#pragma unroll
    for (int off = 16; off; off >>= 1)
        vterm += __shfl_xor_sync(0xffffffffu, vterm, off);
    if (lane == 0) red_sm[warp] = vterm;
    __syncthreads();
    float Z = red_sm[0] + red_sm[1] + red_sm[2] + red_sm[3];
    float partition = Ccum + __logf(Z);
    __syncthreads();

    // ---- gold-path score ----
    const int* tg = tags + b * CRF_S;
    float sc  = 0.0f;
    float nvf = 0.0f;
    for (int s = j; s < CRF_S; s += NT) {
        nvf += msk_sm[s];
        if (s == 0) {
            int t0 = tg[0];
            sc += trans[CRF_SOS * CRF_T + t0] + emb[t0];
        } else {
            int tc = tg[s], tp = tg[s - 1];
            sc += msk_sm[s] * (emb[s * CRF_T + tc] + trans[tp * CRF_T + tc]);
        }
    }
#pragma unroll
    for (int off = 16; off; off >>= 1) {
        sc  += __shfl_xor_sync(0xffffffffu, sc, off);
        nvf += __shfl_xor_sync(0xffffffffu, nvf, off);
    }
    if (lane == 0) { red_sm[warp] = sc; red_sm[4 + warp] = nvf; }
    __syncthreads();
    float SC = red_sm[0] + red_sm[1] + red_sm[2] + red_sm[3];
    float NV = red_sm[4] + red_sm[5] + red_sm[6] + red_sm[7];
    int last = (int)(NV + 0.5f) - 1;
    SC += trans[tg[last] * CRF_T + CRF_EOS];

    if (j == 0) g_part[b] = partition - SC;   // per-batch, no atomics
}

// Deterministic fixed-order final reduction (one warp).
__global__ void crf_reduce(float* __restrict__ out) {
    int l = threadIdx.x;
    float s = 0.0f;
#pragma unroll
    for (int k = 0; k < CRF_B / 32; ++k) s += g_part[l + 32 * k];
#pragma unroll
    for (int off = 16; off; off >>= 1)
        s += __shfl_xor_sync(0xffffffffu, s, off);
    if (l == 0) out[0] = s;
}

extern "C" void kernel_launch(void* const* d_in, const int* in_sizes, int n_in,
                              void* d_out, int out_size) {
    const float* em = (const float*)d_in[0];   // emissions (B,S,T) f32
    const float* tr = (const float*)d_in[1];   // transition (T,T)  f32
    const float* mk = (const float*)d_in[2];   // mask (B,S)        f32
    const int*   tg = (const int*)d_in[3];     // tags (B,S)        i32

    crf_kernel<<<CRF_B, NT>>>(em, tr, mk, tg);
    crf_reduce<<<1, 32>>>((float*)d_out);
}